// round 7
// baseline (speedup 1.0000x reference)
#include <cuda_runtime.h>
#include <cuda_bf16.h>
#include <math.h>
#include <stdint.h>

#define LNUM 8
#define DMODEL 512
#define DINX 1024
#define DSX 16
#define SLEN 256
#define TTOT 512   // BATCH * SLEN tokens

// ---------------- scratch (static device memory; no allocations) ----------------
__device__ float g_meanp[128 * 768];
__device__ float g_imgtok[128 * DMODEL];
__device__ float g_hidden[TTOT * DMODEL];
__device__ float g_resid[TTOT * DMODEL];
__device__ float g_xnorm[TTOT * DMODEL];
__device__ float g_xz[TTOT * 2 * DINX];
__device__ float g_xc[TTOT * DINX];
__device__ float g_proj[TTOT * 64];
__device__ float g_dt[TTOT * DINX];
__device__ float g_y[TTOT * DINX];
__device__ float g_g[TTOT * 2 * DINX];
__device__ float g_Aneg[LNUM * DINX * DSX];
__device__ float g_part[4 * TTOT * DMODEL];   // split-K partial slab (4 MB)
__device__ float g_la[128];

__device__ __forceinline__ float siluf(float x) { return x / (1.0f + __expf(-x)); }
__device__ __forceinline__ float softplusf(float x) {
    return fmaxf(x, 0.0f) + log1pf(__expf(-fabsf(x)));
}

// ---- warp-level bf16 HMMA (sm_80+ PTX; tensor-core path that compiles for sm_103) ----
__device__ __forceinline__ void mma16816(float* c, const uint32_t* a, const uint32_t* b) {
    asm volatile(
        "mma.sync.aligned.m16n8k16.row.col.f32.bf16.bf16.f32 "
        "{%0,%1,%2,%3}, {%4,%5,%6,%7}, {%8,%9}, {%0,%1,%2,%3};"
        : "+f"(c[0]), "+f"(c[1]), "+f"(c[2]), "+f"(c[3])
        : "r"(a[0]), "r"(a[1]), "r"(a[2]), "r"(a[3]), "r"(b[0]), "r"(b[1]));
}

// ============ HMMA GEMM: C[M,N] = A[M,K] @ W[N,K]^T, fp32 via bf16 hi/lo (3 passes) ============
// Grid: (N/64, M/64, splits). Block 128 = 4 warps (2m x 2n), warp tile 32x32.
// BK = 16, double-buffered smem, register prefetch depth 2 (LDG issued 2 chunks ahead).
// AOP: 0 = A[m*lda+k]; 1 = gate y*silu(z); 2 = glu g1*silu(g2)
// EPI: 0 plain store (ldc), 1 +bias, 2 softplus(+bias), 4 split-K partial -> g_part
#define SKA 24   // padded row stride (halves): conflict-free frag LDS
template <int AOP, int EPI>
__global__ void __launch_bounds__(128)
mma_gemm(const float* __restrict__ A, int lda,
         const float* __restrict__ W, int ldb,
         const float* __restrict__ bias,
         float* __restrict__ C, int ldc, int kSpan)
{
    __shared__ __nv_bfloat16 sAh[2][64][SKA];
    __shared__ __nv_bfloat16 sAl[2][64][SKA];
    __shared__ __nv_bfloat16 sBh[2][64][SKA];
    __shared__ __nv_bfloat16 sBl[2][64][SKA];

    const int tid = threadIdx.x;
    const int wid = tid >> 5, lane = tid & 31;
    const int wm = wid >> 1, wn = wid & 1;
    const int grp = lane >> 2, tq = lane & 3;

    const int m0 = blockIdx.y * 64;
    const int n0 = blockIdx.x * 64;
    const int kBase = blockIdx.z * kSpan;
    const int nChunks = kSpan >> 4;

    float acc[2][4][4];
#pragma unroll
    for (int i = 0; i < 2; i++)
#pragma unroll
        for (int j = 0; j < 4; j++)
#pragma unroll
            for (int q = 0; q < 4; q++) acc[i][j][q] = 0.f;

    const int row = tid >> 2;     // 0..31
    const int c4 = tid & 3;       // k-quad within 16-chunk

    auto loadA = [&](int m, int k) -> float4 {
        if constexpr (AOP == 0) {
            return *(const float4*)(A + (size_t)m * lda + k);
        } else if constexpr (AOP == 1) {
            float4 y = *(const float4*)(g_y + (size_t)m * DINX + k);
            float4 z = *(const float4*)(g_xz + (size_t)m * 2048 + 1024 + k);
            return make_float4(y.x * siluf(z.x), y.y * siluf(z.y),
                               y.z * siluf(z.z), y.w * siluf(z.w));
        } else {
            float4 a = *(const float4*)(g_g + (size_t)m * 2048 + k);
            float4 b = *(const float4*)(g_g + (size_t)m * 2048 + 1024 + k);
            return make_float4(a.x * siluf(b.x), a.y * siluf(b.y),
                               a.z * siluf(b.z), a.w * siluf(b.w));
        }
    };

    float4 rg[2][4];   // [stage][A0,A1,B0,B1]
    auto fetch = [&](int c, int s) {
        const int k = kBase + c * 16 + c4 * 4;
        rg[s][0] = loadA(m0 + row, k);
        rg[s][1] = loadA(m0 + 32 + row, k);
        rg[s][2] = *(const float4*)(W + (size_t)(n0 + row) * ldb + k);
        rg[s][3] = *(const float4*)(W + (size_t)(n0 + 32 + row) * ldb + k);
    };
    auto store = [&](int s, int nb) {
        union { __nv_bfloat16 h[4]; uint2 u; } H, L;
#pragma unroll
        for (int i = 0; i < 4; i++) {
            const float4 v = rg[s][i];
            const float vv[4] = {v.x, v.y, v.z, v.w};
#pragma unroll
            for (int q = 0; q < 4; q++) {
                __nv_bfloat16 h = __float2bfloat16(vv[q]);
                H.h[q] = h;
                L.h[q] = __float2bfloat16(vv[q] - __bfloat162float(h));
            }
            const int r = (i & 1) * 32 + row;
            if (i < 2) {
                *(uint2*)&sAh[nb][r][c4 * 4] = H.u;
                *(uint2*)&sAl[nb][r][c4 * 4] = L.u;
            } else {
                *(uint2*)&sBh[nb][r][c4 * 4] = H.u;
                *(uint2*)&sBl[nb][r][c4 * 4] = L.u;
            }
        }
    };

    fetch(0, 0);
    store(0, 0);
    fetch(1, 1);
    __syncthreads();

    for (int c = 0; c < nChunks; c++) {
        const int nb = c & 1;
        // 1. fragment LDS from current buffer
        uint32_t Ah[2][4], Al[2][4], Bh[4][2], Bl[4][2];
#pragma unroll
        for (int mt = 0; mt < 2; mt++) {
            const int r = wm * 32 + mt * 16 + grp;
            Ah[mt][0] = *(const uint32_t*)&sAh[nb][r][2 * tq];
            Ah[mt][1] = *(const uint32_t*)&sAh[nb][r + 8][2 * tq];
            Ah[mt][2] = *(const uint32_t*)&sAh[nb][r][2 * tq + 8];
            Ah[mt][3] = *(const uint32_t*)&sAh[nb][r + 8][2 * tq + 8];
            Al[mt][0] = *(const uint32_t*)&sAl[nb][r][2 * tq];
            Al[mt][1] = *(const uint32_t*)&sAl[nb][r + 8][2 * tq];
            Al[mt][2] = *(const uint32_t*)&sAl[nb][r][2 * tq + 8];
            Al[mt][3] = *(const uint32_t*)&sAl[nb][r + 8][2 * tq + 8];
        }
#pragma unroll
        for (int nt = 0; nt < 4; nt++) {
            const int n = wn * 32 + nt * 8 + grp;
            Bh[nt][0] = *(const uint32_t*)&sBh[nb][n][2 * tq];
            Bh[nt][1] = *(const uint32_t*)&sBh[nb][n][2 * tq + 8];
            Bl[nt][0] = *(const uint32_t*)&sBl[nb][n][2 * tq];
            Bl[nt][1] = *(const uint32_t*)&sBl[nb][n][2 * tq + 8];
        }
        // 2. stage chunk c+1 (already in registers) into the other buffer
        if (c + 1 < nChunks) store((c + 1) & 1, nb ^ 1);
        // 3. issue LDG for chunk c+2 (consumed 2 iterations from now)
        if (c + 2 < nChunks) fetch(c + 2, nb);
        // 4. MMA (3-pass hi/lo)
#pragma unroll
        for (int mt = 0; mt < 2; mt++)
#pragma unroll
            for (int nt = 0; nt < 4; nt++) {
                mma16816(acc[mt][nt], Ah[mt], Bh[nt]);
                mma16816(acc[mt][nt], Ah[mt], Bl[nt]);
                mma16816(acc[mt][nt], Al[mt], Bh[nt]);
            }
        __syncthreads();
    }

    const int Nt = gridDim.x * 64;
    const int Mt = gridDim.y * 64;
#pragma unroll
    for (int mt = 0; mt < 2; mt++) {
#pragma unroll
        for (int nt = 0; nt < 4; nt++) {
            const int col = n0 + wn * 32 + nt * 8 + 2 * tq;
#pragma unroll
            for (int half = 0; half < 2; half++) {
                const int r = m0 + wm * 32 + mt * 16 + grp + half * 8;
                float v0 = acc[mt][nt][half * 2 + 0];
                float v1 = acc[mt][nt][half * 2 + 1];
                if constexpr (EPI == 1) { v0 += bias[col]; v1 += bias[col + 1]; }
                if constexpr (EPI == 2) {
                    v0 = softplusf(v0 + bias[col]);
                    v1 = softplusf(v1 + bias[col + 1]);
                }
                float2 v = make_float2(v0, v1);
                if constexpr (EPI == 4) {
                    *(float2*)(g_part + (size_t)blockIdx.z * Mt * Nt + (size_t)r * Nt + col) = v;
                } else {
                    *(float2*)(C + (size_t)r * ldc + col) = v;
                }
            }
        }
    }
}

__global__ void reduce_part(float* __restrict__ C, int MN, int ns)
{
    int i = blockIdx.x * 256 + threadIdx.x;
    if (i < MN) {
        float s = 0.f;
        for (int z = 0; z < ns; z++) s += g_part[(size_t)z * MN + i];
        C[i] = s;
    }
}

__global__ void reduce_bias(float* __restrict__ C, int MN, int ns,
                            const float* __restrict__ bias, int nmask)
{
    int i = blockIdx.x * 256 + threadIdx.x;
    if (i < MN) {
        float s = bias[i & nmask];
        for (int z = 0; z < ns; z++) s += g_part[(size_t)z * MN + i];
        C[i] = s;
    }
}

// ---------------- tokenize ----------------
__global__ void patch_mean_kernel(const float* __restrict__ images)
{
    const int blc = blockIdx.x;
    const int tid = threadIdx.x;
    const int y = tid >> 4, x = tid & 15;
    const int c = blc % 3, bl = blc / 3;
    const float* base = images + (size_t)blc * 224 * 224;
    float s = 0.f;
#pragma unroll 2
    for (int py = 0; py < 14; py++) {
        const float* row = base + (py * 16 + y) * 224 + x;
#pragma unroll
        for (int px = 0; px < 14; px++) s += row[px * 16];
    }
    g_meanp[(size_t)bl * 768 + c * 256 + tid] = s * (1.0f / 196.0f);
}

__global__ void token_kernel(const float* __restrict__ states,
                             const float* __restrict__ state_w, const float* __restrict__ state_b,
                             const float* __restrict__ actions,
                             const float* __restrict__ act_w, const float* __restrict__ act_b)
{
    const int bl = blockIdx.x;
    const int d = threadIdx.x;
    const int b = bl >> 6, li = bl & 63;
    const int base = b * SLEN + li * 4;

    g_hidden[(size_t)(base + 0) * DMODEL + d] = g_imgtok[(size_t)bl * DMODEL + d];

    const float* st = states + (size_t)bl * 3 * 7;
    float s = state_b[d];
#pragma unroll
    for (int j = 0; j < 7; j++) s = fmaf(st[j], state_w[d * 7 + j], s);
    g_hidden[(size_t)(base + 1) * DMODEL + d] = s;

#pragma unroll
    for (int t = 0; t < 2; t++) {
        const float* ac = actions + (size_t)(bl * 3 + t) * 4;
        float a = act_b[d];
#pragma unroll
        for (int j = 0; j < 4; j++) a = fmaf(ac[j], act_w[d * 4 + j], a);
        g_hidden[(size_t)(base + 2 + t) * DMODEL + d] = a;
    }
}

__global__ void zero_resid_kernel()
{
    int i = blockIdx.x * 256 + threadIdx.x;
    if (i < TTOT * DMODEL) g_resid[i] = 0.f;
}

__global__ void aneg_kernel(const float* __restrict__ A_log)
{
    int i = blockIdx.x * 256 + threadIdx.x;
    if (i < LNUM * DINX * DSX) g_Aneg[i] = -expf(A_log[i]);
}

template <int NS>
__global__ void add_rms_kernel(const float* __restrict__ w)
{
    const int t = blockIdx.x;
    const int tid = threadIdx.x;      // 256
    const size_t base = (size_t)t * DMODEL;
    float a0, a1;
    if (NS == 0) {
        a0 = g_hidden[base + tid];
        a1 = g_hidden[base + 256 + tid];
    } else {
        a0 = 0.f; a1 = 0.f;
#pragma unroll
        for (int z = 0; z < NS; z++) {
            a0 += g_part[(size_t)z * TTOT * DMODEL + base + tid];
            a1 += g_part[(size_t)z * TTOT * DMODEL + base + 256 + tid];
        }
    }
    a0 += g_resid[base + tid];
    a1 += g_resid[base + 256 + tid];
    g_resid[base + tid] = a0;
    g_resid[base + 256 + tid] = a1;
    float ss = a0 * a0 + a1 * a1;
#pragma unroll
    for (int off = 16; off; off >>= 1) ss += __shfl_xor_sync(0xffffffffu, ss, off);
    __shared__ float red[8];
    if ((tid & 31) == 0) red[tid >> 5] = ss;
    __syncthreads();
    float tot = red[0] + red[1] + red[2] + red[3] + red[4] + red[5] + red[6] + red[7];
    float sc = rsqrtf(tot * (1.0f / 512.0f) + 1e-5f);
    g_xnorm[base + tid] = a0 * sc * w[tid];
    g_xnorm[base + 256 + tid] = a1 * sc * w[256 + tid];
}

__global__ void conv_kernel(const float* __restrict__ cw, const float* __restrict__ cb)
{
    int idx = blockIdx.x * 256 + threadIdx.x;
    if (idx >= TTOT * DINX) return;
    const int d = idx & (DINX - 1);
    const int t = idx >> 10;
    const int b = t >> 8, s = t & 255;
    const float* w4 = cw + d * 4;
    float acc = cb[d];
#pragma unroll
    for (int k = 0; k < 4; k++) {
        int ss = s - 3 + k;
        if (ss >= 0) acc = fmaf(w4[k], g_xz[(size_t)(b * SLEN + ss) * 2048 + d], acc);
    }
    g_xc[idx] = siluf(acc);
}

__global__ void scan_kernel(int l, const float* __restrict__ Dp_l)
{
    const int b = blockIdx.y;
    const int d = (blockIdx.x << 4) + (threadIdx.x >> 4);
    const int n = threadIdx.x & 15;
    const float A = g_Aneg[((size_t)l * DINX + d) * DSX + n];
    const float Dv = Dp_l[d];
    float h = 0.f;
    for (int s = 0; s < SLEN; s++) {
        const int t = (b << 8) + s;
        float dtv = __ldg(&g_dt[(size_t)t * DINX + d]);
        float xv  = __ldg(&g_xc[(size_t)t * DINX + d]);
        float Bn  = __ldg(&g_proj[t * 64 + 32 + n]);
        float Cn  = __ldg(&g_proj[t * 64 + 48 + n]);
        float a = __expf(dtv * A);
        h = fmaf(a, h, dtv * Bn * xv);
        float c = h * Cn;
        c += __shfl_down_sync(0xffffffffu, c, 8, 16);
        c += __shfl_down_sync(0xffffffffu, c, 4, 16);
        c += __shfl_down_sync(0xffffffffu, c, 2, 16);
        c += __shfl_down_sync(0xffffffffu, c, 1, 16);
        if (n == 0) g_y[(size_t)t * DINX + d] = fmaf(Dv, xv, c);
    }
}

// ---------------- head + loss ----------------
__global__ void head_kernel(const float* __restrict__ head_w, const float* __restrict__ head_b,
                            const float* __restrict__ labels,
                            float* __restrict__ out, int ofs, int write_preds)
{
    const int bl = blockIdx.x;
    const int w = threadIdx.x >> 5;
    const int lane = threadIdx.x & 31;
    const int t = w >> 2, a = w & 3;
    const int b = bl >> 6, li = bl & 63;
    const int tok = b * SLEN + li * 4 + 1 + t;
    const float* x = g_xnorm + (size_t)tok * DMODEL;
    const float* hw = head_w + a * DMODEL;
    float s = 0.f;
    for (int i = lane; i < DMODEL; i += 32) s = fmaf(x[i], hw[i], s);
#pragma unroll
    for (int off = 16; off; off >>= 1) s += __shfl_xor_sync(0xffffffffu, s, off);
    __shared__ float sd[12];
    if (lane == 0) {
        float pred = s + head_b[a];
        int idx = bl * 12 + t * 4 + a;
        if (write_preds) out[ofs + idx] = pred;
        sd[w] = fabsf(pred - labels[idx]);
    }
    __syncthreads();
    if (threadIdx.x == 0) {
        float acc = 0.f;
#pragma unroll
        for (int i = 0; i < 12; i++) acc += sd[i];
        g_la[bl] = acc * (1.0f / 12.0f);
    }
}

__global__ void loss_kernel(const int* __restrict__ seqlen, float* __restrict__ out, int write_loss)
{
    const int tid = threadIdx.x;
    const int b = tid >> 6, li = tid & 63;
    float m = (li < seqlen[b]) ? 1.f : 0.f;
    __shared__ float sv[128], sm[128];
    sv[tid] = g_la[tid] * m;
    sm[tid] = m;
    __syncthreads();
    if (tid == 0 && write_loss) {
        float s0 = 0, c0 = 0, s1 = 0, c1 = 0;
        for (int i = 0; i < 64; i++) { s0 += sv[i]; c0 += sm[i]; s1 += sv[64 + i]; c1 += sm[64 + i]; }
        float l0 = s0 / fmaxf(c0, 1.f);
        float l1 = s1 / fmaxf(c1, 1.f);
        out[0] = 0.5f * (l0 + l1);
    }
}

// ---------------- host ----------------
extern "C" void kernel_launch(void* const* d_in, const int* in_sizes, int n_in,
                              void* d_out, int out_size)
{
    const float* images   = (const float*)d_in[0];
    const int*   seqlen   = (const int*)  d_in[1];
    const float* states   = (const float*)d_in[2];
    const float* actions  = (const float*)d_in[3];
    const float* labels   = (const float*)d_in[4];
    const float* patch_w  = (const float*)d_in[5];
    const float* patch_b  = (const float*)d_in[6];
    const float* state_w  = (const float*)d_in[7];
    const float* state_b  = (const float*)d_in[8];
    const float* act_w    = (const float*)d_in[9];
    const float* act_b    = (const float*)d_in[10];
    const float* norm1_w  = (const float*)d_in[11];
    const float* in_proj_w= (const float*)d_in[12];
    const float* conv_w   = (const float*)d_in[13];
    const float* conv_b   = (const float*)d_in[14];
    const float* x_proj_w = (const float*)d_in[15];
    const float* dt_w     = (const float*)d_in[16];
    const float* dt_b     = (const float*)d_in[17];
    const float* A_log    = (const float*)d_in[18];
    const float* Dp       = (const float*)d_in[19];
    const float* out_proj_w=(const float*)d_in[20];
    const float* norm2_w  = (const float*)d_in[21];
    const float* fc1_w    = (const float*)d_in[22];
    const float* fc2_w    = (const float*)d_in[23];
    const float* norm_f_w = (const float*)d_in[24];
    const float* head_w   = (const float*)d_in[25];
    const float* head_b   = (const float*)d_in[26];
    float* out = (float*)d_out;

    float *p_meanp, *p_imgtok, *p_xnorm, *p_xz, *p_xc, *p_proj, *p_dt, *p_g;
    cudaGetSymbolAddress((void**)&p_meanp, g_meanp);
    cudaGetSymbolAddress((void**)&p_imgtok, g_imgtok);
    cudaGetSymbolAddress((void**)&p_xnorm, g_xnorm);
    cudaGetSymbolAddress((void**)&p_xz, g_xz);
    cudaGetSymbolAddress((void**)&p_xc, g_xc);
    cudaGetSymbolAddress((void**)&p_proj, g_proj);
    cudaGetSymbolAddress((void**)&p_dt, g_dt);
    cudaGetSymbolAddress((void**)&p_g, g_g);

    // prologue
    zero_resid_kernel<<<(TTOT * DMODEL + 255) / 256, 256>>>();
    aneg_kernel<<<(LNUM * DINX * DSX + 255) / 256, 256>>>(A_log);
    patch_mean_kernel<<<384, 256>>>(images);
    // img tokens: [128,512] = meanp[128,768] @ patch_w^T + patch_b  (split-K 4)
    mma_gemm<0,4><<<dim3(8, 2, 4), 128>>>(p_meanp, 768, patch_w, 768,
                                          nullptr, nullptr, 512, 192);
    reduce_bias<<<(128 * 512 + 255) / 256, 256>>>(p_imgtok, 128 * 512, 4, patch_b, 511);
    token_kernel<<<128, 512>>>(states, state_w, state_b, actions, act_w, act_b);

    for (int l = 0; l < LNUM; l++) {
        if (l == 0) add_rms_kernel<0><<<TTOT, 256>>>(norm1_w);
        else        add_rms_kernel<4><<<TTOT, 256>>>(norm1_w + l * DMODEL);
        // xz[512,2048] = xnorm @ in_proj^T (K=512)
        mma_gemm<0,0><<<dim3(32, 8, 1), 128>>>(p_xnorm, 512,
            in_proj_w + (size_t)l * 2048 * 512, 512, nullptr, p_xz, 2048, 512);
        conv_kernel<<<(TTOT * DINX + 255) / 256, 256>>>(conv_w + (size_t)l * DINX * 4,
                                                        conv_b + l * DINX);
        // proj[512,64] = xc @ x_proj^T (K=1024, split-K 8)
        mma_gemm<0,4><<<dim3(1, 8, 8), 128>>>(p_xc, 1024,
            x_proj_w + (size_t)l * 64 * 1024, 1024, nullptr, nullptr, 64, 128);
        reduce_part<<<(TTOT * 64 + 255) / 256, 256>>>(p_proj, TTOT * 64, 8);
        // dt[512,1024] = softplus(dtr @ dt_w^T + dt_b); dtr = proj[:, :32] (lda=64)
        mma_gemm<0,2><<<dim3(16, 8, 1), 128>>>(p_proj, 64,
            dt_w + (size_t)l * 1024 * 32, 32, dt_b + l * DINX, p_dt, 1024, 32);
        scan_kernel<<<dim3(64, 2), 256>>>(l, Dp + l * DINX);
        // hidden_partials = (y*silu(z)) @ out_proj^T (K=1024, split-K 4, gate fused in A)
        mma_gemm<1,4><<<dim3(8, 8, 4), 128>>>(nullptr, 0,
            out_proj_w + (size_t)l * 512 * 1024, 1024, nullptr, nullptr, 512, 256);
        add_rms_kernel<4><<<TTOT, 256>>>(norm2_w + l * DMODEL);
        // g[512,2048] = xnorm @ fc1^T (K=512)
        mma_gemm<0,0><<<dim3(32, 8, 1), 128>>>(p_xnorm, 512,
            fc1_w + (size_t)l * 2048 * 512, 512, nullptr, p_g, 2048, 512);
        // hidden_partials = (g1*silu(g2)) @ fc2^T (K=1024, split-K 4, GLU fused in A)
        mma_gemm<2,4><<<dim3(8, 8, 4), 128>>>(nullptr, 0,
            fc2_w + (size_t)l * 512 * 1024, 1024, nullptr, nullptr, 512, 256);
    }

    // final norm + head + loss
    add_rms_kernel<4><<<TTOT, 256>>>(norm_f_w);
    int write_preds = (out_size >= 1536) ? 1 : 0;
    int ofs = (out_size == 1536) ? 0 : 1;
    int write_loss = (out_size != 1536) ? 1 : 0;
    head_kernel<<<128, 384>>>(head_w, head_b, labels, out, ofs, write_preds);
    loss_kernel<<<1, 128>>>(seqlen, out, write_loss);
}

// round 8
// speedup vs baseline: 1.2885x; 1.2885x over previous
#include <cuda_runtime.h>
#include <cuda_fp16.h>
#include <math.h>
#include <stdint.h>

#define LNUM 8
#define DMODEL 512
#define DINX 1024
#define DSX 16
#define SLEN 256
#define TTOT 512   // BATCH * SLEN tokens

// ---------------- scratch (static device memory; no allocations) ----------------
__device__ float g_meanp[128 * 768];
__device__ float g_imgtok[128 * DMODEL];
__device__ float g_hidden[TTOT * DMODEL];
__device__ float g_resid[TTOT * DMODEL];
__device__ float g_xnorm[TTOT * DMODEL];
__device__ float g_xz[TTOT * 2 * DINX];
__device__ float g_xc[TTOT * DINX];
__device__ float g_proj[TTOT * 64];
__device__ float g_dt[TTOT * DINX];
__device__ float g_y[TTOT * DINX];
__device__ float g_g[TTOT * 2 * DINX];
__device__ float g_Aneg[LNUM * DINX * DSX];
__device__ float g_part[4 * TTOT * DMODEL];   // split-K partial slab (4 MB)
__device__ float g_la[128];

__device__ __forceinline__ float siluf(float x) { return x / (1.0f + __expf(-x)); }
__device__ __forceinline__ float softplusf(float x) {
    return fmaxf(x, 0.0f) + log1pf(__expf(-fabsf(x)));
}

// ---- warp-level fp16 HMMA (sm_80+ PTX; tensor-core path that compiles for sm_103) ----
__device__ __forceinline__ void mma16816(float* c, const uint32_t* a, const uint32_t* b) {
    asm volatile(
        "mma.sync.aligned.m16n8k16.row.col.f32.f16.f16.f32 "
        "{%0,%1,%2,%3}, {%4,%5,%6,%7}, {%8,%9}, {%0,%1,%2,%3};"
        : "+f"(c[0]), "+f"(c[1]), "+f"(c[2]), "+f"(c[3])
        : "r"(a[0]), "r"(a[1]), "r"(a[2]), "r"(a[3]), "r"(b[0]), "r"(b[1]));
}

// ====== HMMA GEMM: C[M,N] = A[M,K] @ W[N,K]^T, fp32 accuracy via A=hi+lo fp16, 2 passes ======
// Grid: (N/64, M/64, splits). Block 256 = 8 warps (4m x 2n), warp tile 16x32.
// BK = 16, double-buffered smem, register prefetch depth 2.
// AOP: 0 = A[m*lda+k]; 1 = gate y*silu(z); 2 = glu g1*silu(g2)
// EPI: 0 plain store (ldc), 1 +bias, 2 softplus(+bias), 4 split-K partial -> g_part
#define SKA 24   // padded row stride (halves): conflict-free frag LDS
template <int AOP, int EPI>
__global__ void __launch_bounds__(256)
mma_gemm(const float* __restrict__ A, int lda,
         const float* __restrict__ W, int ldb,
         const float* __restrict__ bias,
         float* __restrict__ C, int ldc, int kSpan)
{
    __shared__ __half sAh[2][64][SKA];
    __shared__ __half sAl[2][64][SKA];
    __shared__ __half sB [2][64][SKA];

    const int tid = threadIdx.x;
    const int wid = tid >> 5, lane = tid & 31;
    const int wm = wid >> 1, wn = wid & 1;       // 4 m-tiles x 2 n-tiles
    const int grp = lane >> 2, tq = lane & 3;

    const int m0 = blockIdx.y * 64;
    const int n0 = blockIdx.x * 64;
    const int kBase = blockIdx.z * kSpan;
    const int nChunks = kSpan >> 4;

    float acc[4][4];
#pragma unroll
    for (int j = 0; j < 4; j++)
#pragma unroll
        for (int q = 0; q < 4; q++) acc[j][q] = 0.f;

    const int row = tid >> 2;     // 0..63
    const int c4 = tid & 3;       // k-quad within 16-chunk

    auto loadA = [&](int m, int k) -> float4 {
        if constexpr (AOP == 0) {
            return *(const float4*)(A + (size_t)m * lda + k);
        } else if constexpr (AOP == 1) {
            float4 y = *(const float4*)(g_y + (size_t)m * DINX + k);
            float4 z = *(const float4*)(g_xz + (size_t)m * 2048 + 1024 + k);
            return make_float4(y.x * siluf(z.x), y.y * siluf(z.y),
                               y.z * siluf(z.z), y.w * siluf(z.w));
        } else {
            float4 a = *(const float4*)(g_g + (size_t)m * 2048 + k);
            float4 b = *(const float4*)(g_g + (size_t)m * 2048 + 1024 + k);
            return make_float4(a.x * siluf(b.x), a.y * siluf(b.y),
                               a.z * siluf(b.z), a.w * siluf(b.w));
        }
    };

    float4 rgA[2], rgB[2];
    auto fetch = [&](int c, int s) {
        const int k = kBase + c * 16 + c4 * 4;
        rgA[s] = loadA(m0 + row, k);
        rgB[s] = *(const float4*)(W + (size_t)(n0 + row) * ldb + k);
    };
    auto store = [&](int s, int nb) {
        {   // A: hi/lo split
            const float4 v = rgA[s];
            const float vv[4] = {v.x, v.y, v.z, v.w};
            union { __half h[4]; uint2 u; } H, L;
#pragma unroll
            for (int q = 0; q < 4; q++) {
                __half h = __float2half_rn(vv[q]);
                H.h[q] = h;
                L.h[q] = __float2half_rn(vv[q] - __half2float(h));
            }
            *(uint2*)&sAh[nb][row][c4 * 4] = H.u;
            *(uint2*)&sAl[nb][row][c4 * 4] = L.u;
        }
        {   // B: single fp16
            const float4 v = rgB[s];
            union { __half h[4]; uint2 u; } Hb;
            Hb.h[0] = __float2half_rn(v.x); Hb.h[1] = __float2half_rn(v.y);
            Hb.h[2] = __float2half_rn(v.z); Hb.h[3] = __float2half_rn(v.w);
            *(uint2*)&sB[nb][row][c4 * 4] = Hb.u;
        }
    };

    fetch(0, 0);
    store(0, 0);
    if (nChunks > 1) fetch(1, 1);
    __syncthreads();

    for (int c = 0; c < nChunks; c++) {
        const int nb = c & 1;
        // fragments (conflict-free padded LDS): A tile 16 rows, B tiles 4 x 8 cols
        uint32_t Ah[4], Al[4], Bf[4][2];
        {
            const int r = wm * 16 + grp;
            Ah[0] = *(const uint32_t*)&sAh[nb][r][2 * tq];
            Ah[1] = *(const uint32_t*)&sAh[nb][r + 8][2 * tq];
            Ah[2] = *(const uint32_t*)&sAh[nb][r][2 * tq + 8];
            Ah[3] = *(const uint32_t*)&sAh[nb][r + 8][2 * tq + 8];
            Al[0] = *(const uint32_t*)&sAl[nb][r][2 * tq];
            Al[1] = *(const uint32_t*)&sAl[nb][r + 8][2 * tq];
            Al[2] = *(const uint32_t*)&sAl[nb][r][2 * tq + 8];
            Al[3] = *(const uint32_t*)&sAl[nb][r + 8][2 * tq + 8];
        }
#pragma unroll
        for (int nt = 0; nt < 4; nt++) {
            const int col = wn * 32 + nt * 8 + grp;
            Bf[nt][0] = *(const uint32_t*)&sB[nb][col][2 * tq];
            Bf[nt][1] = *(const uint32_t*)&sB[nb][col][2 * tq + 8];
        }
        // stage chunk c+1 (in registers) into other buffer; prefetch chunk c+2
        if (c + 1 < nChunks) store((c + 1) & 1, nb ^ 1);
        if (c + 2 < nChunks) fetch(c + 2, nb);
        // 2-pass MMA: hi + lo
#pragma unroll
        for (int nt = 0; nt < 4; nt++) {
            mma16816(acc[nt], Ah, Bf[nt]);
            mma16816(acc[nt], Al, Bf[nt]);
        }
        __syncthreads();
    }

    const int Nt = gridDim.x * 64;
    const int Mt = gridDim.y * 64;
#pragma unroll
    for (int nt = 0; nt < 4; nt++) {
        const int col = n0 + wn * 32 + nt * 8 + 2 * tq;
#pragma unroll
        for (int half = 0; half < 2; half++) {
            const int r = m0 + wm * 16 + grp + half * 8;
            float v0 = acc[nt][half * 2 + 0];
            float v1 = acc[nt][half * 2 + 1];
            if constexpr (EPI == 1) { v0 += bias[col]; v1 += bias[col + 1]; }
            if constexpr (EPI == 2) {
                v0 = softplusf(v0 + bias[col]);
                v1 = softplusf(v1 + bias[col + 1]);
            }
            float2 v = make_float2(v0, v1);
            if constexpr (EPI == 4) {
                *(float2*)(g_part + (size_t)blockIdx.z * Mt * Nt + (size_t)r * Nt + col) = v;
            } else {
                *(float2*)(C + (size_t)r * ldc + col) = v;
            }
        }
    }
}

__global__ void reduce_part(float* __restrict__ C, int MN, int ns)
{
    int i = blockIdx.x * 256 + threadIdx.x;
    if (i < MN) {
        float s = 0.f;
        for (int z = 0; z < ns; z++) s += g_part[(size_t)z * MN + i];
        C[i] = s;
    }
}

__global__ void reduce_bias(float* __restrict__ C, int MN, int ns,
                            const float* __restrict__ bias, int nmask)
{
    int i = blockIdx.x * 256 + threadIdx.x;
    if (i < MN) {
        float s = bias[i & nmask];
        for (int z = 0; z < ns; z++) s += g_part[(size_t)z * MN + i];
        C[i] = s;
    }
}

// ---------------- tokenize ----------------
__global__ void patch_mean_kernel(const float* __restrict__ images)
{
    const int blc = blockIdx.x;
    const int tid = threadIdx.x;
    const int y = tid >> 4, x = tid & 15;
    const int c = blc % 3, bl = blc / 3;
    const float* base = images + (size_t)blc * 224 * 224;
    float s = 0.f;
#pragma unroll 2
    for (int py = 0; py < 14; py++) {
        const float* row = base + (py * 16 + y) * 224 + x;
#pragma unroll
        for (int px = 0; px < 14; px++) s += row[px * 16];
    }
    g_meanp[(size_t)bl * 768 + c * 256 + tid] = s * (1.0f / 196.0f);
}

__global__ void token_kernel(const float* __restrict__ states,
                             const float* __restrict__ state_w, const float* __restrict__ state_b,
                             const float* __restrict__ actions,
                             const float* __restrict__ act_w, const float* __restrict__ act_b)
{
    const int bl = blockIdx.x;
    const int d = threadIdx.x;
    const int b = bl >> 6, li = bl & 63;
    const int base = b * SLEN + li * 4;

    g_hidden[(size_t)(base + 0) * DMODEL + d] = g_imgtok[(size_t)bl * DMODEL + d];

    const float* st = states + (size_t)bl * 3 * 7;
    float s = state_b[d];
#pragma unroll
    for (int j = 0; j < 7; j++) s = fmaf(st[j], state_w[d * 7 + j], s);
    g_hidden[(size_t)(base + 1) * DMODEL + d] = s;

#pragma unroll
    for (int t = 0; t < 2; t++) {
        const float* ac = actions + (size_t)(bl * 3 + t) * 4;
        float a = act_b[d];
#pragma unroll
        for (int j = 0; j < 4; j++) a = fmaf(ac[j], act_w[d * 4 + j], a);
        g_hidden[(size_t)(base + 2 + t) * DMODEL + d] = a;
    }
}

__global__ void zero_resid_kernel()
{
    int i = blockIdx.x * 256 + threadIdx.x;
    if (i < TTOT * DMODEL) g_resid[i] = 0.f;
}

__global__ void aneg_kernel(const float* __restrict__ A_log)
{
    int i = blockIdx.x * 256 + threadIdx.x;
    if (i < LNUM * DINX * DSX) g_Aneg[i] = -expf(A_log[i]);
}

template <int NS>
__global__ void add_rms_kernel(const float* __restrict__ w)
{
    const int t = blockIdx.x;
    const int tid = threadIdx.x;      // 256
    const size_t base = (size_t)t * DMODEL;
    float a0, a1;
    if (NS == 0) {
        a0 = g_hidden[base + tid];
        a1 = g_hidden[base + 256 + tid];
    } else {
        a0 = 0.f; a1 = 0.f;
#pragma unroll
        for (int z = 0; z < NS; z++) {
            a0 += g_part[(size_t)z * TTOT * DMODEL + base + tid];
            a1 += g_part[(size_t)z * TTOT * DMODEL + base + 256 + tid];
        }
    }
    a0 += g_resid[base + tid];
    a1 += g_resid[base + 256 + tid];
    g_resid[base + tid] = a0;
    g_resid[base + 256 + tid] = a1;
    float ss = a0 * a0 + a1 * a1;
#pragma unroll
    for (int off = 16; off; off >>= 1) ss += __shfl_xor_sync(0xffffffffu, ss, off);
    __shared__ float red[8];
    if ((tid & 31) == 0) red[tid >> 5] = ss;
    __syncthreads();
    float tot = red[0] + red[1] + red[2] + red[3] + red[4] + red[5] + red[6] + red[7];
    float sc = rsqrtf(tot * (1.0f / 512.0f) + 1e-5f);
    g_xnorm[base + tid] = a0 * sc * w[tid];
    g_xnorm[base + 256 + tid] = a1 * sc * w[256 + tid];
}

__global__ void conv_kernel(const float* __restrict__ cw, const float* __restrict__ cb)
{
    int idx = blockIdx.x * 256 + threadIdx.x;
    if (idx >= TTOT * DINX) return;
    const int d = idx & (DINX - 1);
    const int t = idx >> 10;
    const int b = t >> 8, s = t & 255;
    const float* w4 = cw + d * 4;
    float acc = cb[d];
#pragma unroll
    for (int k = 0; k < 4; k++) {
        int ss = s - 3 + k;
        if (ss >= 0) acc = fmaf(w4[k], g_xz[(size_t)(b * SLEN + ss) * 2048 + d], acc);
    }
    g_xc[idx] = siluf(acc);
}

// ---------------- selective scan (smem-tiled, double-buffered) ----------------
// Grid (64, 2), block 256 = 16 d-channels x 16 states.
__global__ void scan_kernel(int l, const float* __restrict__ Dp_l)
{
    const int b = blockIdx.y;
    const int d0 = blockIdx.x << 4;
    const int tid = threadIdx.x;
    const int d = tid >> 4, n = tid & 15;
    const float Aa = g_Aneg[((size_t)l * DINX + d0 + d) * DSX + n];
    const float Dv = Dp_l[d0 + d];

    __shared__ float sdt[2][32][16], sxc[2][32][16], sBt[2][32][16], sCt[2][32][16];

    float r0[4], r1[4];
    const int ls = tid >> 4, ld = tid & 15;   // staging coords: step ls(+16), chan ld
    auto fetchT = [&](int tile) {
        const int t0 = (b << 8) + (tile << 5);
        r0[0] = g_dt[(size_t)(t0 + ls) * DINX + d0 + ld];
        r0[1] = g_xc[(size_t)(t0 + ls) * DINX + d0 + ld];
        r0[2] = g_proj[(t0 + ls) * 64 + 32 + ld];
        r0[3] = g_proj[(t0 + ls) * 64 + 48 + ld];
        r1[0] = g_dt[(size_t)(t0 + 16 + ls) * DINX + d0 + ld];
        r1[1] = g_xc[(size_t)(t0 + 16 + ls) * DINX + d0 + ld];
        r1[2] = g_proj[(t0 + 16 + ls) * 64 + 32 + ld];
        r1[3] = g_proj[(t0 + 16 + ls) * 64 + 48 + ld];
    };
    auto commitT = [&](int buf) {
        sdt[buf][ls][ld] = r0[0]; sxc[buf][ls][ld] = r0[1];
        sBt[buf][ls][ld] = r0[2]; sCt[buf][ls][ld] = r0[3];
        sdt[buf][ls + 16][ld] = r1[0]; sxc[buf][ls + 16][ld] = r1[1];
        sBt[buf][ls + 16][ld] = r1[2]; sCt[buf][ls + 16][ld] = r1[3];
    };

    fetchT(0); commitT(0);
    fetchT(1);
    __syncthreads();

    float h = 0.f;
    for (int tile = 0; tile < 8; tile++) {
        const int buf = tile & 1;
        const int t0 = (b << 8) + (tile << 5);
#pragma unroll 8
        for (int s = 0; s < 32; s++) {
            float dtv = sdt[buf][s][d];
            float xv  = sxc[buf][s][d];
            float Bn  = sBt[buf][s][n];
            float Cn  = sCt[buf][s][n];
            float a = __expf(dtv * Aa);
            h = fmaf(a, h, dtv * Bn * xv);
            float c = h * Cn;
            c += __shfl_down_sync(0xffffffffu, c, 8, 16);
            c += __shfl_down_sync(0xffffffffu, c, 4, 16);
            c += __shfl_down_sync(0xffffffffu, c, 2, 16);
            c += __shfl_down_sync(0xffffffffu, c, 1, 16);
            if (n == 0) g_y[(size_t)(t0 + s) * DINX + d0 + d] = fmaf(Dv, xv, c);
        }
        __syncthreads();
        if (tile + 1 < 8) {
            commitT((tile + 1) & 1);
            if (tile + 2 < 8) fetchT(tile + 2);
            __syncthreads();
        }
    }
}

// ---------------- head + loss ----------------
__global__ void head_kernel(const float* __restrict__ head_w, const float* __restrict__ head_b,
                            const float* __restrict__ labels,
                            float* __restrict__ out, int ofs, int write_preds)
{
    const int bl = blockIdx.x;
    const int w = threadIdx.x >> 5;
    const int lane = threadIdx.x & 31;
    const int t = w >> 2, a = w & 3;
    const int b = bl >> 6, li = bl & 63;
    const int tok = b * SLEN + li * 4 + 1 + t;
    const float* x = g_xnorm + (size_t)tok * DMODEL;
    const float* hw = head_w + a * DMODEL;
    float s = 0.f;
    for (int i = lane; i < DMODEL; i += 32) s = fmaf(x[i], hw[i], s);
#pragma unroll
    for (int off = 16; off; off >>= 1) s += __shfl_xor_sync(0xffffffffu, s, off);
    __shared__ float sd[12];
    if (lane == 0) {
        float pred = s + head_b[a];
        int idx = bl * 12 + t * 4 + a;
        if (write_preds) out[ofs + idx] = pred;
        sd[w] = fabsf(pred - labels[idx]);
    }
    __syncthreads();
    if (threadIdx.x == 0) {
        float acc = 0.f;
#pragma unroll
        for (int i = 0; i < 12; i++) acc += sd[i];
        g_la[bl] = acc * (1.0f / 12.0f);
    }
}

__global__ void loss_kernel(const int* __restrict__ seqlen, float* __restrict__ out, int write_loss)
{
    const int tid = threadIdx.x;
    const int b = tid >> 6, li = tid & 63;
    float m = (li < seqlen[b]) ? 1.f : 0.f;
    __shared__ float sv[128], sm[128];
    sv[tid] = g_la[tid] * m;
    sm[tid] = m;
    __syncthreads();
    if (tid == 0 && write_loss) {
        float s0 = 0, c0 = 0, s1 = 0, c1 = 0;
        for (int i = 0; i < 64; i++) { s0 += sv[i]; c0 += sm[i]; s1 += sv[64 + i]; c1 += sm[64 + i]; }
        float l0 = s0 / fmaxf(c0, 1.f);
        float l1 = s1 / fmaxf(c1, 1.f);
        out[0] = 0.5f * (l0 + l1);
    }
}

// ---------------- host ----------------
extern "C" void kernel_launch(void* const* d_in, const int* in_sizes, int n_in,
                              void* d_out, int out_size)
{
    const float* images   = (const float*)d_in[0];
    const int*   seqlen   = (const int*)  d_in[1];
    const float* states   = (const float*)d_in[2];
    const float* actions  = (const float*)d_in[3];
    const float* labels   = (const float*)d_in[4];
    const float* patch_w  = (const float*)d_in[5];
    const float* patch_b  = (const float*)d_in[6];
    const float* state_w  = (const float*)d_in[7];
    const float* state_b  = (const float*)d_in[8];
    const float* act_w    = (const float*)d_in[9];
    const float* act_b    = (const float*)d_in[10];
    const float* norm1_w  = (const float*)d_in[11];
    const float* in_proj_w= (const float*)d_in[12];
    const float* conv_w   = (const float*)d_in[13];
    const float* conv_b   = (const float*)d_in[14];
    const float* x_proj_w = (const float*)d_in[15];
    const float* dt_w     = (const float*)d_in[16];
    const float* dt_b     = (const float*)d_in[17];
    const float* A_log    = (const float*)d_in[18];
    const float* Dp       = (const float*)d_in[19];
    const float* out_proj_w=(const float*)d_in[20];
    const float* norm2_w  = (const float*)d_in[21];
    const float* fc1_w    = (const float*)d_in[22];
    const float* fc2_w    = (const float*)d_in[23];
    const float* norm_f_w = (const float*)d_in[24];
    const float* head_w   = (const float*)d_in[25];
    const float* head_b   = (const float*)d_in[26];
    float* out = (float*)d_out;

    float *p_meanp, *p_imgtok, *p_xnorm, *p_xz, *p_xc, *p_proj, *p_dt, *p_g;
    cudaGetSymbolAddress((void**)&p_meanp, g_meanp);
    cudaGetSymbolAddress((void**)&p_imgtok, g_imgtok);
    cudaGetSymbolAddress((void**)&p_xnorm, g_xnorm);
    cudaGetSymbolAddress((void**)&p_xz, g_xz);
    cudaGetSymbolAddress((void**)&p_xc, g_xc);
    cudaGetSymbolAddress((void**)&p_proj, g_proj);
    cudaGetSymbolAddress((void**)&p_dt, g_dt);
    cudaGetSymbolAddress((void**)&p_g, g_g);

    // prologue
    zero_resid_kernel<<<(TTOT * DMODEL + 255) / 256, 256>>>();
    aneg_kernel<<<(LNUM * DINX * DSX + 255) / 256, 256>>>(A_log);
    patch_mean_kernel<<<384, 256>>>(images);
    // img tokens: [128,512] = meanp[128,768] @ patch_w^T + patch_b  (split-K 4)
    mma_gemm<0,4><<<dim3(8, 2, 4), 256>>>(p_meanp, 768, patch_w, 768,
                                          nullptr, nullptr, 512, 192);
    reduce_bias<<<(128 * 512 + 255) / 256, 256>>>(p_imgtok, 128 * 512, 4, patch_b, 511);
    token_kernel<<<128, 512>>>(states, state_w, state_b, actions, act_w, act_b);

    for (int l = 0; l < LNUM; l++) {
        if (l == 0) add_rms_kernel<0><<<TTOT, 256>>>(norm1_w);
        else        add_rms_kernel<4><<<TTOT, 256>>>(norm1_w + l * DMODEL);
        // xz[512,2048] = xnorm @ in_proj^T (K=512)
        mma_gemm<0,0><<<dim3(32, 8, 1), 256>>>(p_xnorm, 512,
            in_proj_w + (size_t)l * 2048 * 512, 512, nullptr, p_xz, 2048, 512);
        conv_kernel<<<(TTOT * DINX + 255) / 256, 256>>>(conv_w + (size_t)l * DINX * 4,
                                                        conv_b + l * DINX);
        // proj[512,64] = xc @ x_proj^T (K=1024, split-K 8)
        mma_gemm<0,4><<<dim3(1, 8, 8), 256>>>(p_xc, 1024,
            x_proj_w + (size_t)l * 64 * 1024, 1024, nullptr, nullptr, 64, 128);
        reduce_part<<<(TTOT * 64 + 255) / 256, 256>>>(p_proj, TTOT * 64, 8);
        // dt[512,1024] = softplus(dtr @ dt_w^T + dt_b); dtr = proj[:, :32] (lda=64)
        mma_gemm<0,2><<<dim3(16, 8, 1), 256>>>(p_proj, 64,
            dt_w + (size_t)l * 1024 * 32, 32, dt_b + l * DINX, p_dt, 1024, 32);
        scan_kernel<<<dim3(64, 2), 256>>>(l, Dp + l * DINX);
        // hidden_partials = (y*silu(z)) @ out_proj^T (K=1024, split-K 4, gate fused in A)
        mma_gemm<1,4><<<dim3(8, 8, 4), 256>>>(nullptr, 0,
            out_proj_w + (size_t)l * 512 * 1024, 1024, nullptr, nullptr, 512, 256);
        add_rms_kernel<4><<<TTOT, 256>>>(norm2_w + l * DMODEL);
        // g[512,2048] = xnorm @ fc1^T (K=512)
        mma_gemm<0,0><<<dim3(32, 8, 1), 256>>>(p_xnorm, 512,
            fc1_w + (size_t)l * 2048 * 512, 512, nullptr, p_g, 2048, 512);
        // hidden_partials = (g1*silu(g2)) @ fc2^T (K=1024, split-K 4, GLU fused in A)
        mma_gemm<2,4><<<dim3(8, 8, 4), 256>>>(nullptr, 0,
            fc2_w + (size_t)l * 512 * 1024, 1024, nullptr, nullptr, 512, 256);
    }

    // final norm + head + loss
    add_rms_kernel<4><<<TTOT, 256>>>(norm_f_w);
    int write_preds = (out_size >= 1536) ? 1 : 0;
    int ofs = (out_size == 1536) ? 0 : 1;
    int write_loss = (out_size != 1536) ? 1 : 0;
    head_kernel<<<128, 384>>>(head_w, head_b, labels, out, ofs, write_preds);
    loss_kernel<<<1, 128>>>(seqlen, out, write_loss);
}

// round 9
// speedup vs baseline: 1.3109x; 1.0174x over previous
#include <cuda_runtime.h>
#include <cuda_fp16.h>
#include <math.h>
#include <stdint.h>

#define LNUM 8
#define DMODEL 512
#define DINX 1024
#define DSX 16
#define SLEN 256
#define TTOT 512   // BATCH * SLEN tokens

// ---------------- scratch (static device memory; no allocations) ----------------
__device__ float g_meanp[128 * 768];
__device__ float g_imgtok[128 * DMODEL];
__device__ float g_hidden[TTOT * DMODEL];
__device__ float g_resid[TTOT * DMODEL];
__device__ float g_xnorm[TTOT * DMODEL];
__device__ float g_xz[TTOT * 2 * DINX];
__device__ float g_xc[TTOT * DINX];
__device__ float g_proj[TTOT * 64];
__device__ float g_dt[TTOT * DINX];
__device__ float g_y[TTOT * DINX];
__device__ float g_g[TTOT * 2 * DINX];
__device__ float g_Aneg[LNUM * DINX * DSX];
__device__ float g_part[4 * TTOT * DMODEL];   // split-K partial slab (4 MB)
__device__ float g_la[128];

__device__ __forceinline__ float siluf(float x) { return x / (1.0f + __expf(-x)); }
__device__ __forceinline__ float softplusf(float x) {
    return fmaxf(x, 0.0f) + log1pf(__expf(-fabsf(x)));
}

// ---- warp-level fp16 HMMA (sm_80+ PTX; tensor-core path that compiles for sm_103) ----
__device__ __forceinline__ void mma16816(float* c, const uint32_t* a, const uint32_t* b) {
    asm volatile(
        "mma.sync.aligned.m16n8k16.row.col.f32.f16.f16.f32 "
        "{%0,%1,%2,%3}, {%4,%5,%6,%7}, {%8,%9}, {%0,%1,%2,%3};"
        : "+f"(c[0]), "+f"(c[1]), "+f"(c[2]), "+f"(c[3])
        : "r"(a[0]), "r"(a[1]), "r"(a[2]), "r"(a[3]), "r"(b[0]), "r"(b[1]));
}

// ====== HMMA GEMM: C[M,N] = A[M,K] @ W[N,K]^T ======
// fp32 accuracy via fp16 hi/lo split of BOTH operands; 3 MMA passes (hh, lh, hl),
// dropped ll term error ~2^-22.
// Grid: (N/64, M/64, splits). Block 256 = 8 warps (4m x 2n), warp tile 16x32.
// BK = 16, double-buffered smem, 4-stage register prefetch (true distance 2).
// AOP: 0 = A[m*lda+k]; 1 = gate y*silu(z); 2 = glu g1*silu(g2)
// EPI: 0 plain store (ldc), 1 +bias, 2 softplus(+bias), 4 split-K partial -> g_part
#define SKA 24   // padded row stride (halves): conflict-free frag LDS
template <int AOP, int EPI>
__global__ void __launch_bounds__(256, 2)
mma_gemm(const float* __restrict__ A, int lda,
         const float* __restrict__ W, int ldb,
         const float* __restrict__ bias,
         float* __restrict__ C, int ldc, int kSpan)
{
    __shared__ __half sAh[2][64][SKA];
    __shared__ __half sAl[2][64][SKA];
    __shared__ __half sBh[2][64][SKA];
    __shared__ __half sBl[2][64][SKA];

    const int tid = threadIdx.x;
    const int wid = tid >> 5, lane = tid & 31;
    const int wm = wid >> 1, wn = wid & 1;       // 4 m-tiles x 2 n-tiles
    const int grp = lane >> 2, tq = lane & 3;

    const int m0 = blockIdx.y * 64;
    const int n0 = blockIdx.x * 64;
    const int kBase = blockIdx.z * kSpan;
    const int nChunks = kSpan >> 4;

    float acc[4][4];
#pragma unroll
    for (int j = 0; j < 4; j++)
#pragma unroll
        for (int q = 0; q < 4; q++) acc[j][q] = 0.f;

    const int row = tid >> 2;     // 0..63
    const int c4 = tid & 3;       // k-quad within 16-chunk

    auto loadA = [&](int m, int k) -> float4 {
        if constexpr (AOP == 0) {
            return *(const float4*)(A + (size_t)m * lda + k);
        } else if constexpr (AOP == 1) {
            float4 y = *(const float4*)(g_y + (size_t)m * DINX + k);
            float4 z = *(const float4*)(g_xz + (size_t)m * 2048 + 1024 + k);
            return make_float4(y.x * siluf(z.x), y.y * siluf(z.y),
                               y.z * siluf(z.z), y.w * siluf(z.w));
        } else {
            float4 a = *(const float4*)(g_g + (size_t)m * 2048 + k);
            float4 b = *(const float4*)(g_g + (size_t)m * 2048 + 1024 + k);
            return make_float4(a.x * siluf(b.x), a.y * siluf(b.y),
                               a.z * siluf(b.z), a.w * siluf(b.w));
        }
    };

    float4 rgA[4], rgB[4];         // 4-stage register pipeline
    auto fetch = [&](int c, int s) {
        const int k = kBase + c * 16 + c4 * 4;
        rgA[s] = loadA(m0 + row, k);
        rgB[s] = *(const float4*)(W + (size_t)(n0 + row) * ldb + k);
    };
    auto store = [&](int s, int nb) {
        {   // A hi/lo
            const float4 v = rgA[s];
            const float vv[4] = {v.x, v.y, v.z, v.w};
            union { __half h[4]; uint2 u; } H, L;
#pragma unroll
            for (int q = 0; q < 4; q++) {
                __half h = __float2half_rn(vv[q]);
                H.h[q] = h;
                L.h[q] = __float2half_rn(vv[q] - __half2float(h));
            }
            *(uint2*)&sAh[nb][row][c4 * 4] = H.u;
            *(uint2*)&sAl[nb][row][c4 * 4] = L.u;
        }
        {   // B hi/lo
            const float4 v = rgB[s];
            const float vv[4] = {v.x, v.y, v.z, v.w};
            union { __half h[4]; uint2 u; } H, L;
#pragma unroll
            for (int q = 0; q < 4; q++) {
                __half h = __float2half_rn(vv[q]);
                H.h[q] = h;
                L.h[q] = __float2half_rn(vv[q] - __half2float(h));
            }
            *(uint2*)&sBh[nb][row][c4 * 4] = H.u;
            *(uint2*)&sBl[nb][row][c4 * 4] = L.u;
        }
    };

    fetch(0, 0);
    store(0, 0);
    if (nChunks > 1) fetch(1, 1);
    if (nChunks > 2) fetch(2, 2);
    __syncthreads();

    for (int c = 0; c < nChunks; c++) {
        const int nb = c & 1;
        // fragments (padded LDS): A tile 16 rows (per wm), B 4 x 8-col tiles (per wn)
        uint32_t Ah[4], Al[4], Bh[4][2], Bl[4][2];
        {
            const int r = wm * 16 + grp;
            Ah[0] = *(const uint32_t*)&sAh[nb][r][2 * tq];
            Ah[1] = *(const uint32_t*)&sAh[nb][r + 8][2 * tq];
            Ah[2] = *(const uint32_t*)&sAh[nb][r][2 * tq + 8];
            Ah[3] = *(const uint32_t*)&sAh[nb][r + 8][2 * tq + 8];
            Al[0] = *(const uint32_t*)&sAl[nb][r][2 * tq];
            Al[1] = *(const uint32_t*)&sAl[nb][r + 8][2 * tq];
            Al[2] = *(const uint32_t*)&sAl[nb][r][2 * tq + 8];
            Al[3] = *(const uint32_t*)&sAl[nb][r + 8][2 * tq + 8];
        }
#pragma unroll
        for (int nt = 0; nt < 4; nt++) {
            const int col = wn * 32 + nt * 8 + grp;
            Bh[nt][0] = *(const uint32_t*)&sBh[nb][col][2 * tq];
            Bh[nt][1] = *(const uint32_t*)&sBh[nb][col][2 * tq + 8];
            Bl[nt][0] = *(const uint32_t*)&sBl[nb][col][2 * tq];
            Bl[nt][1] = *(const uint32_t*)&sBl[nb][col][2 * tq + 8];
        }
        // stage chunk c+1 (fetched 2 iterations ago) into other smem buffer
        if (c + 1 < nChunks) store((c + 1) & 3, nb ^ 1);
        // issue LDG for chunk c+3 (consumed at iteration c+2)
        if (c + 3 < nChunks) fetch(c + 3, (c + 3) & 3);
        // 3-pass MMA: hh + lh + hl
#pragma unroll
        for (int nt = 0; nt < 4; nt++) {
            mma16816(acc[nt], Ah, Bh[nt]);
            mma16816(acc[nt], Al, Bh[nt]);
            mma16816(acc[nt], Ah, Bl[nt]);
        }
        __syncthreads();
    }

    const int Nt = gridDim.x * 64;
    const int Mt = gridDim.y * 64;
#pragma unroll
    for (int nt = 0; nt < 4; nt++) {
        const int col = n0 + wn * 32 + nt * 8 + 2 * tq;
#pragma unroll
        for (int half = 0; half < 2; half++) {
            const int r = m0 + wm * 16 + grp + half * 8;
            float v0 = acc[nt][half * 2 + 0];
            float v1 = acc[nt][half * 2 + 1];
            if constexpr (EPI == 1) { v0 += bias[col]; v1 += bias[col + 1]; }
            if constexpr (EPI == 2) {
                v0 = softplusf(v0 + bias[col]);
                v1 = softplusf(v1 + bias[col + 1]);
            }
            float2 v = make_float2(v0, v1);
            if constexpr (EPI == 4) {
                *(float2*)(g_part + (size_t)blockIdx.z * Mt * Nt + (size_t)r * Nt + col) = v;
            } else {
                *(float2*)(C + (size_t)r * ldc + col) = v;
            }
        }
    }
}

__global__ void reduce_part(float* __restrict__ C, int MN, int ns)
{
    int i = blockIdx.x * 256 + threadIdx.x;
    if (i < MN) {
        float s = 0.f;
        for (int z = 0; z < ns; z++) s += g_part[(size_t)z * MN + i];
        C[i] = s;
    }
}

__global__ void reduce_bias(float* __restrict__ C, int MN, int ns,
                            const float* __restrict__ bias, int nmask)
{
    int i = blockIdx.x * 256 + threadIdx.x;
    if (i < MN) {
        float s = bias[i & nmask];
        for (int z = 0; z < ns; z++) s += g_part[(size_t)z * MN + i];
        C[i] = s;
    }
}

// ---------------- tokenize ----------------
__global__ void patch_mean_kernel(const float* __restrict__ images)
{
    const int blc = blockIdx.x;
    const int tid = threadIdx.x;
    const int y = tid >> 4, x = tid & 15;
    const int c = blc % 3, bl = blc / 3;
    const float* base = images + (size_t)blc * 224 * 224;
    float s = 0.f;
#pragma unroll 2
    for (int py = 0; py < 14; py++) {
        const float* row = base + (py * 16 + y) * 224 + x;
#pragma unroll
        for (int px = 0; px < 14; px++) s += row[px * 16];
    }
    g_meanp[(size_t)bl * 768 + c * 256 + tid] = s * (1.0f / 196.0f);
}

__global__ void token_kernel(const float* __restrict__ states,
                             const float* __restrict__ state_w, const float* __restrict__ state_b,
                             const float* __restrict__ actions,
                             const float* __restrict__ act_w, const float* __restrict__ act_b)
{
    const int bl = blockIdx.x;
    const int d = threadIdx.x;
    const int b = bl >> 6, li = bl & 63;
    const int base = b * SLEN + li * 4;

    g_hidden[(size_t)(base + 0) * DMODEL + d] = g_imgtok[(size_t)bl * DMODEL + d];

    const float* st = states + (size_t)bl * 3 * 7;
    float s = state_b[d];
#pragma unroll
    for (int j = 0; j < 7; j++) s = fmaf(st[j], state_w[d * 7 + j], s);
    g_hidden[(size_t)(base + 1) * DMODEL + d] = s;

#pragma unroll
    for (int t = 0; t < 2; t++) {
        const float* ac = actions + (size_t)(bl * 3 + t) * 4;
        float a = act_b[d];
#pragma unroll
        for (int j = 0; j < 4; j++) a = fmaf(ac[j], act_w[d * 4 + j], a);
        g_hidden[(size_t)(base + 2 + t) * DMODEL + d] = a;
    }
}

__global__ void aneg_kernel(const float* __restrict__ A_log)
{
    int i = blockIdx.x * 256 + threadIdx.x;
    if (i < LNUM * DINX * DSX) g_Aneg[i] = -expf(A_log[i]);
}

// residual += hidden (g_hidden if NS==0, else sum of NS split-K partials);
// NS==0 also means residual starts at zero (first layer) — no resid read.
template <int NS>
__global__ void add_rms_kernel(const float* __restrict__ w)
{
    const int t = blockIdx.x;
    const int tid = threadIdx.x;      // 256
    const size_t base = (size_t)t * DMODEL;
    float a0, a1;
    if (NS == 0) {
        a0 = g_hidden[base + tid];
        a1 = g_hidden[base + 256 + tid];
    } else {
        a0 = 0.f; a1 = 0.f;
#pragma unroll
        for (int z = 0; z < NS; z++) {
            a0 += g_part[(size_t)z * TTOT * DMODEL + base + tid];
            a1 += g_part[(size_t)z * TTOT * DMODEL + base + 256 + tid];
        }
        a0 += g_resid[base + tid];
        a1 += g_resid[base + 256 + tid];
    }
    g_resid[base + tid] = a0;
    g_resid[base + 256 + tid] = a1;
    float ss = a0 * a0 + a1 * a1;
#pragma unroll
    for (int off = 16; off; off >>= 1) ss += __shfl_xor_sync(0xffffffffu, ss, off);
    __shared__ float red[8];
    if ((tid & 31) == 0) red[tid >> 5] = ss;
    __syncthreads();
    float tot = red[0] + red[1] + red[2] + red[3] + red[4] + red[5] + red[6] + red[7];
    float sc = rsqrtf(tot * (1.0f / 512.0f) + 1e-5f);
    g_xnorm[base + tid] = a0 * sc * w[tid];
    g_xnorm[base + 256 + tid] = a1 * sc * w[256 + tid];
}

__global__ void conv_kernel(const float* __restrict__ cw, const float* __restrict__ cb)
{
    int idx = blockIdx.x * 256 + threadIdx.x;
    if (idx >= TTOT * DINX) return;
    const int d = idx & (DINX - 1);
    const int t = idx >> 10;
    const int b = t >> 8, s = t & 255;
    const float* w4 = cw + d * 4;
    float acc = cb[d];
#pragma unroll
    for (int k = 0; k < 4; k++) {
        int ss = s - 3 + k;
        if (ss >= 0) acc = fmaf(w4[k], g_xz[(size_t)(b * SLEN + ss) * 2048 + d], acc);
    }
    g_xc[idx] = siluf(acc);
}

// ---------------- selective scan (smem-tiled, double-buffered) ----------------
// Grid (64, 2), block 256 = 16 d-channels x 16 states.
__global__ void scan_kernel(int l, const float* __restrict__ Dp_l)
{
    const int b = blockIdx.y;
    const int d0 = blockIdx.x << 4;
    const int tid = threadIdx.x;
    const int d = tid >> 4, n = tid & 15;
    const float Aa = g_Aneg[((size_t)l * DINX + d0 + d) * DSX + n];
    const float Dv = Dp_l[d0 + d];

    __shared__ float sdt[2][32][16], sxc[2][32][16], sBt[2][32][16], sCt[2][32][16];

    float r0[4], r1[4];
    const int ls = tid >> 4, ld = tid & 15;   // staging coords
    auto fetchT = [&](int tile) {
        const int t0 = (b << 8) + (tile << 5);
        r0[0] = g_dt[(size_t)(t0 + ls) * DINX + d0 + ld];
        r0[1] = g_xc[(size_t)(t0 + ls) * DINX + d0 + ld];
        r0[2] = g_proj[(t0 + ls) * 64 + 32 + ld];
        r0[3] = g_proj[(t0 + ls) * 64 + 48 + ld];
        r1[0] = g_dt[(size_t)(t0 + 16 + ls) * DINX + d0 + ld];
        r1[1] = g_xc[(size_t)(t0 + 16 + ls) * DINX + d0 + ld];
        r1[2] = g_proj[(t0 + 16 + ls) * 64 + 32 + ld];
        r1[3] = g_proj[(t0 + 16 + ls) * 64 + 48 + ld];
    };
    auto commitT = [&](int buf) {
        sdt[buf][ls][ld] = r0[0]; sxc[buf][ls][ld] = r0[1];
        sBt[buf][ls][ld] = r0[2]; sCt[buf][ls][ld] = r0[3];
        sdt[buf][ls + 16][ld] = r1[0]; sxc[buf][ls + 16][ld] = r1[1];
        sBt[buf][ls + 16][ld] = r1[2]; sCt[buf][ls + 16][ld] = r1[3];
    };

    fetchT(0); commitT(0);
    fetchT(1);
    __syncthreads();

    float h = 0.f;
    for (int tile = 0; tile < 8; tile++) {
        const int buf = tile & 1;
        const int t0 = (b << 8) + (tile << 5);
#pragma unroll 8
        for (int s = 0; s < 32; s++) {
            float dtv = sdt[buf][s][d];
            float xv  = sxc[buf][s][d];
            float Bn  = sBt[buf][s][n];
            float Cn  = sCt[buf][s][n];
            float a = __expf(dtv * Aa);
            h = fmaf(a, h, dtv * Bn * xv);
            float c = h * Cn;
            c += __shfl_down_sync(0xffffffffu, c, 8, 16);
            c += __shfl_down_sync(0xffffffffu, c, 4, 16);
            c += __shfl_down_sync(0xffffffffu, c, 2, 16);
            c += __shfl_down_sync(0xffffffffu, c, 1, 16);
            if (n == 0) g_y[(size_t)(t0 + s) * DINX + d0 + d] = fmaf(Dv, xv, c);
        }
        __syncthreads();
        if (tile + 1 < 8) {
            commitT((tile + 1) & 1);
            if (tile + 2 < 8) fetchT(tile + 2);
            __syncthreads();
        }
    }
}

// ---------------- head + loss ----------------
__global__ void head_kernel(const float* __restrict__ head_w, const float* __restrict__ head_b,
                            const float* __restrict__ labels,
                            float* __restrict__ out, int ofs, int write_preds)
{
    const int bl = blockIdx.x;
    const int w = threadIdx.x >> 5;
    const int lane = threadIdx.x & 31;
    const int t = w >> 2, a = w & 3;
    const int b = bl >> 6, li = bl & 63;
    const int tok = b * SLEN + li * 4 + 1 + t;
    const float* x = g_xnorm + (size_t)tok * DMODEL;
    const float* hw = head_w + a * DMODEL;
    float s = 0.f;
    for (int i = lane; i < DMODEL; i += 32) s = fmaf(x[i], hw[i], s);
#pragma unroll
    for (int off = 16; off; off >>= 1) s += __shfl_xor_sync(0xffffffffu, s, off);
    __shared__ float sd[12];
    if (lane == 0) {
        float pred = s + head_b[a];
        int idx = bl * 12 + t * 4 + a;
        if (write_preds) out[ofs + idx] = pred;
        sd[w] = fabsf(pred - labels[idx]);
    }
    __syncthreads();
    if (threadIdx.x == 0) {
        float acc = 0.f;
#pragma unroll
        for (int i = 0; i < 12; i++) acc += sd[i];
        g_la[bl] = acc * (1.0f / 12.0f);
    }
}

__global__ void loss_kernel(const int* __restrict__ seqlen, float* __restrict__ out, int write_loss)
{
    const int tid = threadIdx.x;
    const int b = tid >> 6, li = tid & 63;
    float m = (li < seqlen[b]) ? 1.f : 0.f;
    __shared__ float sv[128], sm[128];
    sv[tid] = g_la[tid] * m;
    sm[tid] = m;
    __syncthreads();
    if (tid == 0 && write_loss) {
        float s0 = 0, c0 = 0, s1 = 0, c1 = 0;
        for (int i = 0; i < 64; i++) { s0 += sv[i]; c0 += sm[i]; s1 += sv[64 + i]; c1 += sm[64 + i]; }
        float l0 = s0 / fmaxf(c0, 1.f);
        float l1 = s1 / fmaxf(c1, 1.f);
        out[0] = 0.5f * (l0 + l1);
    }
}

// ---------------- host ----------------
extern "C" void kernel_launch(void* const* d_in, const int* in_sizes, int n_in,
                              void* d_out, int out_size)
{
    const float* images   = (const float*)d_in[0];
    const int*   seqlen   = (const int*)  d_in[1];
    const float* states   = (const float*)d_in[2];
    const float* actions  = (const float*)d_in[3];
    const float* labels   = (const float*)d_in[4];
    const float* patch_w  = (const float*)d_in[5];
    const float* patch_b  = (const float*)d_in[6];
    const float* state_w  = (const float*)d_in[7];
    const float* state_b  = (const float*)d_in[8];
    const float* act_w    = (const float*)d_in[9];
    const float* act_b    = (const float*)d_in[10];
    const float* norm1_w  = (const float*)d_in[11];
    const float* in_proj_w= (const float*)d_in[12];
    const float* conv_w   = (const float*)d_in[13];
    const float* conv_b   = (const float*)d_in[14];
    const float* x_proj_w = (const float*)d_in[15];
    const float* dt_w     = (const float*)d_in[16];
    const float* dt_b     = (const float*)d_in[17];
    const float* A_log    = (const float*)d_in[18];
    const float* Dp       = (const float*)d_in[19];
    const float* out_proj_w=(const float*)d_in[20];
    const float* norm2_w  = (const float*)d_in[21];
    const float* fc1_w    = (const float*)d_in[22];
    const float* fc2_w    = (const float*)d_in[23];
    const float* norm_f_w = (const float*)d_in[24];
    const float* head_w   = (const float*)d_in[25];
    const float* head_b   = (const float*)d_in[26];
    float* out = (float*)d_out;

    float *p_meanp, *p_imgtok, *p_xnorm, *p_xz, *p_xc, *p_proj, *p_dt, *p_g;
    cudaGetSymbolAddress((void**)&p_meanp, g_meanp);
    cudaGetSymbolAddress((void**)&p_imgtok, g_imgtok);
    cudaGetSymbolAddress((void**)&p_xnorm, g_xnorm);
    cudaGetSymbolAddress((void**)&p_xz, g_xz);
    cudaGetSymbolAddress((void**)&p_xc, g_xc);
    cudaGetSymbolAddress((void**)&p_proj, g_proj);
    cudaGetSymbolAddress((void**)&p_dt, g_dt);
    cudaGetSymbolAddress((void**)&p_g, g_g);

    // prologue
    aneg_kernel<<<(LNUM * DINX * DSX + 255) / 256, 256>>>(A_log);
    patch_mean_kernel<<<384, 256>>>(images);
    // img tokens: [128,512] = meanp[128,768] @ patch_w^T + patch_b  (split-K 4)
    mma_gemm<0,4><<<dim3(8, 2, 4), 256>>>(p_meanp, 768, patch_w, 768,
                                          nullptr, nullptr, 512, 192);
    reduce_bias<<<(128 * 512 + 255) / 256, 256>>>(p_imgtok, 128 * 512, 4, patch_b, 511);
    token_kernel<<<128, 512>>>(states, state_w, state_b, actions, act_w, act_b);

    for (int l = 0; l < LNUM; l++) {
        if (l == 0) add_rms_kernel<0><<<TTOT, 256>>>(norm1_w);
        else        add_rms_kernel<4><<<TTOT, 256>>>(norm1_w + l * DMODEL);
        // xz[512,2048] = xnorm @ in_proj^T (K=512)
        mma_gemm<0,0><<<dim3(32, 8, 1), 256>>>(p_xnorm, 512,
            in_proj_w + (size_t)l * 2048 * 512, 512, nullptr, p_xz, 2048, 512);
        conv_kernel<<<(TTOT * DINX + 255) / 256, 256>>>(conv_w + (size_t)l * DINX * 4,
                                                        conv_b + l * DINX);
        // proj[512,64] = xc @ x_proj^T (K=1024, split-K 8)
        mma_gemm<0,4><<<dim3(1, 8, 8), 256>>>(p_xc, 1024,
            x_proj_w + (size_t)l * 64 * 1024, 1024, nullptr, nullptr, 64, 128);
        reduce_part<<<(TTOT * 64 + 255) / 256, 256>>>(p_proj, TTOT * 64, 8);
        // dt[512,1024] = softplus(dtr @ dt_w^T + dt_b); dtr = proj[:, :32] (lda=64)
        mma_gemm<0,2><<<dim3(16, 8, 1), 256>>>(p_proj, 64,
            dt_w + (size_t)l * 1024 * 32, 32, dt_b + l * DINX, p_dt, 1024, 32);
        scan_kernel<<<dim3(64, 2), 256>>>(l, Dp + l * DINX);
        // hidden_partials = (y*silu(z)) @ out_proj^T (K=1024, split-K 4, gate fused in A)
        mma_gemm<1,4><<<dim3(8, 8, 4), 256>>>(nullptr, 0,
            out_proj_w + (size_t)l * 512 * 1024, 1024, nullptr, nullptr, 512, 256);
        add_rms_kernel<4><<<TTOT, 256>>>(norm2_w + l * DMODEL);
        // g[512,2048] = xnorm @ fc1^T (K=512)
        mma_gemm<0,0><<<dim3(32, 8, 1), 256>>>(p_xnorm, 512,
            fc1_w + (size_t)l * 2048 * 512, 512, nullptr, p_g, 2048, 512);
        // hidden_partials = (g1*silu(g2)) @ fc2^T (K=1024, split-K 4, GLU fused in A)
        mma_gemm<2,4><<<dim3(8, 8, 4), 256>>>(nullptr, 0,
            fc2_w + (size_t)l * 512 * 1024, 1024, nullptr, nullptr, 512, 256);
    }

    // final norm + head + loss
    add_rms_kernel<4><<<TTOT, 256>>>(norm_f_w);
    int write_preds = (out_size >= 1536) ? 1 : 0;
    int ofs = (out_size == 1536) ? 0 : 1;
    int write_loss = (out_size != 1536) ? 1 : 0;
    head_kernel<<<128, 384>>>(head_w, head_b, labels, out, ofs, write_preds);
    loss_kernel<<<1, 128>>>(seqlen, out, write_loss);
}